// round 15
// baseline (speedup 1.0000x reference)
#include <cuda_runtime.h>
#include <math.h>

#define NPTS   2048
#define NT     128
#define NW     (NT/32)      // 4 warps
#define MAXPTS 100
#define F_INF  (__int_as_float(0x7f800000))

typedef unsigned long long u64;
typedef unsigned int       u32;

static __device__ __forceinline__ u64 umax64(u64 a, u64 b) { return a > b ? a : b; }

template<int E> struct Regs { float x2[E], y2[E], z2[E], sq[E], mk[E]; };

// per-thread argmin: fold tail onto largest pow2 <= E, then halve (compare-select)
template<int E>
static __device__ __forceinline__ void argmin_tree(const float (&v)[E],
                                                   float& outv, int& outi)
{
    float bv[E]; int bi[E];
    #pragma unroll
    for (int e = 0; e < E; e++) { bv[e] = v[e]; bi[e] = e; }
    constexpr int T = ((E & (E - 1)) == 0) ? E : (E > 8 ? 8 : (E > 4 ? 4 : 2));
    #pragma unroll
    for (int e = T; e < E; e++) {
        bool c = bv[e] < bv[e - T];
        bv[e - T] = c ? bv[e] : bv[e - T];
        bi[e - T] = c ? bi[e] : bi[e - T];
    }
    #pragma unroll
    for (int st = T / 2; st >= 1; st >>= 1) {
        #pragma unroll
        for (int e = 0; e < st; e++) {
            bool c = bv[e + st] < bv[e];
            bv[e] = c ? bv[e + st] : bv[e];
            bi[e] = c ? bi[e + st] : bi[e];
        }
    }
    outv = bv[0]; outi = bi[0];
}

// ---------- multi-warp Prim phase ----------
// tbl = raw (x,y,z,|x|^2); regs hold -2x. Broadcast coords carried in q across steps;
// post-barrier: speculative loads of all 4 candidates overlap the value tree.
template<int E>
static __device__ __forceinline__ void prim_run(
    const float4* __restrict__ tbl, float* __restrict__ sdeath,
    u64 (&wred)[2][NW], Regs<E>& R,
    int gbase, int tid, int wid,
    int& j, int& p, int step0, int nsteps)
{
    const float inf = F_INF;
    float4 q = tbl[j];
    #pragma unroll 1
    for (int s = 0; s < nsteps; s++) {
        #pragma unroll
        for (int e = 0; e < E; e++) {
            int gi = gbase + e;
            bool rem = (gi == j);
            float rs = rem ? inf : R.sq[e];       // permanent poison of removed vertex
            R.sq[e] = rs;
            float acc = fmaf(q.x, R.x2[e], rs + q.w);
            acc = fmaf(q.y, R.y2[e], acc);
            acc = fmaf(q.z, R.z2[e], acc);
            float mi = rem ? inf : R.mk[e];
            R.mk[e] = fminf(mi, fabsf(acc));      // >=0 -> u32 bit-order exact
        }
        float tm; int te;
        argmin_tree<E>(R.mk, tm, te);
        u32 ti = (u32)(gbase + te);
        u32 vb = __float_as_uint(tm);
        u32 r1 = __reduce_min_sync(0xffffffffu, vb);
        if (vb == r1) wred[p][wid] = ((u64)r1 << 32) | (u64)ti;  // atomic STS.64: pair consistent

        __syncthreads();

        ulonglong2 wa = *reinterpret_cast<const ulonglong2*>(&wred[p][0]);
        ulonglong2 wb = *reinterpret_cast<const ulonglong2*>(&wred[p][2]);
        u32 v0 = (u32)(wa.x >> 32), i0 = (u32)wa.x;
        u32 v1 = (u32)(wa.y >> 32), i1 = (u32)wa.y;
        u32 v2 = (u32)(wb.x >> 32), i2 = (u32)wb.x;
        u32 v3 = (u32)(wb.y >> 32), i3 = (u32)wb.y;
        // speculative broadcast loads (overlap the value tree below)
        float4 q0 = tbl[i0], q1 = tbl[i1], q2 = tbl[i2], q3 = tbl[i3];
        bool c01 = v1 < v0;
        u32 va = c01 ? v1 : v0;  u32 ia = c01 ? i1 : i0;
        bool c23 = v3 < v2;
        u32 vc = c23 ? v3 : v2;  u32 ic = c23 ? i3 : i2;
        bool cf = vc < va;
        u32 vf = cf ? vc : va;
        j = (int)(cf ? ic : ia);
        float4 qa, qc;
        qa.x = c01 ? q1.x : q0.x; qa.y = c01 ? q1.y : q0.y;
        qa.z = c01 ? q1.z : q0.z; qa.w = c01 ? q1.w : q0.w;
        qc.x = c23 ? q3.x : q2.x; qc.y = c23 ? q3.y : q2.y;
        qc.z = c23 ? q3.z : q2.z; qc.w = c23 ? q3.w : q2.w;
        q.x = cf ? qc.x : qa.x; q.y = cf ? qc.y : qa.y;
        q.z = cf ? qc.z : qa.z; q.w = cf ? qc.w : qa.w;

        if (tid == 0) sdeath[step0 + s] = __uint_as_float(vf);
        p ^= 1;
    }
}

// ---------- single-warp Prim phase (warp 0, no block barriers) ----------
template<int E>
static __device__ __forceinline__ void prim_warp(
    const float4* __restrict__ tbl, float* __restrict__ sdeath,
    Regs<E>& R, int gbase, int lane, int& j, int step0, int nsteps)
{
    const float inf = F_INF;
    float4 q = tbl[j];
    #pragma unroll 1
    for (int s = 0; s < nsteps; s++) {
        #pragma unroll
        for (int e = 0; e < E; e++) {
            int gi = gbase + e;
            bool rem = (gi == j);
            float rs = rem ? inf : R.sq[e];
            R.sq[e] = rs;
            float acc = fmaf(q.x, R.x2[e], rs + q.w);
            acc = fmaf(q.y, R.y2[e], acc);
            acc = fmaf(q.z, R.z2[e], acc);
            float mi = rem ? inf : R.mk[e];
            R.mk[e] = fminf(mi, fabsf(acc));
        }
        float tm; int te;
        argmin_tree<E>(R.mk, tm, te);
        float4 myq = tbl[gbase + te];             // speculative; overlaps REDUX
        u32 vb = __float_as_uint(tm);
        u32 r1 = __reduce_min_sync(0xffffffffu, vb);
        u32 msk = __ballot_sync(0xffffffffu, vb == r1);
        int src = __ffs(msk) - 1;
        j   = __shfl_sync(0xffffffffu, gbase + te, src);
        q.x = __shfl_sync(0xffffffffu, myq.x, src);
        q.y = __shfl_sync(0xffffffffu, myq.y, src);
        q.z = __shfl_sync(0xffffffffu, myq.z, src);
        q.w = __shfl_sync(0xffffffffu, myq.w, src);
        if (lane == 0) sdeath[step0 + s] = __uint_as_float(r1);
    }
}

// ---------- block-wide compaction: alive -> tbl[0..newcap-2], winner at newcap-1 ----------
template<int E>
static __device__ __forceinline__ void compact_block(
    float4* tbl, float* smk, int* scnt,
    Regs<E>& R, int gbase, int tid, int j, int newcap)
{
    const float inf = F_INF;
    #pragma unroll
    for (int e = 0; e < E; e++)
        if (gbase + e == j) { R.sq[e] = inf; R.mk[e] = inf; }   // pending poison
    float4 win = tbl[j];                    // read winner BEFORE overwrite
    __syncthreads();
    if (tid == 0) { tbl[newcap - 1] = win; smk[newcap - 1] = inf; }
    int na = 0;
    #pragma unroll
    for (int e = 0; e < E; e++) na += (R.mk[e] != inf);
    int base = atomicAdd(scnt, na);
    #pragma unroll
    for (int e = 0; e < E; e++) {
        if (R.mk[e] != inf) {
            tbl[base] = make_float4(-0.5f * R.x2[e], -0.5f * R.y2[e],
                                    -0.5f * R.z2[e], R.sq[e]);
            smk[base] = R.mk[e];
            base++;
        }
    }
    __syncthreads();
}

// ---------- warp-0-only compaction ----------
template<int E>
static __device__ __forceinline__ void compact_warp(
    float4* tbl, float* smk, int* scnt,
    Regs<E>& R, int gbase, int lane, int j, int newcap)
{
    const float inf = F_INF;
    #pragma unroll
    for (int e = 0; e < E; e++)
        if (gbase + e == j) { R.sq[e] = inf; R.mk[e] = inf; }
    float4 win = tbl[j];
    __syncwarp();
    if (lane == 0) { tbl[newcap - 1] = win; smk[newcap - 1] = inf; }
    int na = 0;
    #pragma unroll
    for (int e = 0; e < E; e++) na += (R.mk[e] != inf);
    int base = atomicAdd(scnt, na);
    #pragma unroll
    for (int e = 0; e < E; e++) {
        if (R.mk[e] != inf) {
            tbl[base] = make_float4(-0.5f * R.x2[e], -0.5f * R.y2[e],
                                    -0.5f * R.z2[e], R.sq[e]);
            smk[base] = R.mk[e];
            base++;
        }
    }
    __syncwarp();
}

template<int E>
static __device__ __forceinline__ void reload(
    const float4* tbl, const float* smk, Regs<E>& R, int gbase, int cap)
{
    #pragma unroll
    for (int e = 0; e < E; e++) {
        int i = gbase + e;
        float4 t = tbl[i];
        R.x2[e] = -2.0f * t.x; R.y2[e] = -2.0f * t.y; R.z2[e] = -2.0f * t.z;
        R.sq[e] = (i == cap - 1) ? F_INF : t.w;     // winner pad inert
        R.mk[e] = smk[i];
    }
}

// ---------- recursive staircase: phase at cap=E*128 (128 steps), compact, descend ----------
template<int E>
struct Chain {
    static __device__ __forceinline__ void go(
        float4* tbl, float* smk, float* sdeath, u64 (&wred)[2][NW], int* scnt,
        int tid, int wid, int& j, int& p, int step0)
    {
        Regs<E> R;
        reload<E>(tbl, smk, R, tid * E, E * 128);
        prim_run<E>(tbl, sdeath, wred, R, tid * E, tid, wid, j, p, step0, 128);
        if constexpr (E > 3) {
            compact_block<E>(tbl, smk, &scnt[E], R, tid * E, tid, j, (E - 1) * 128);
            j = (E - 1) * 128 - 1;
            Chain<E - 1>::go(tbl, smk, sdeath, wred, scnt, tid, wid, j, p, step0 + 128);
        } else {
            compact_block<3>(tbl, smk, &scnt[3], R, tid * 3, tid, j, 256);
            j = 255;
        }
    }
};

__global__ __launch_bounds__(NT, 1)
void ph_kernel(const float* __restrict__ x,
               const float* __restrict__ filt,
               float* __restrict__ out,
               int B, int F)
{
    __shared__ __align__(16) float4 tbl[NPTS];     // raw (x,y,z,|x|^2), reused
    __shared__ __align__(16) float  sdeath[NPTS];
    __shared__ float  smk[1920];
    __shared__ __align__(16) u64 wred[2][NW];
    __shared__ int    scnt[17];
    __shared__ int    bcnt[64];

    const int b     = blockIdx.x;
    const int tid   = threadIdx.x;
    const int lane  = tid & 31;
    const int wid   = tid >> 5;
    const float inf = F_INF;

    const float* xb = x + (long)b * NPTS * 3;

    // ---- load: premultiplied regs (E=16), raw table ----
    Regs<16> R1;
    {
        int gbase = tid << 4;
        #pragma unroll
        for (int e = 0; e < 16; e++) {
            int i = gbase + e;
            float a = xb[3*i + 0];
            float c = xb[3*i + 1];
            float d = xb[3*i + 2];
            float s = fmaf(a, a, fmaf(c, c, d * d));
            R1.x2[e] = -2.0f * a; R1.y2[e] = -2.0f * c; R1.z2[e] = -2.0f * d;
            R1.sq[e] = s; R1.mk[e] = inf;
            tbl[i] = make_float4(a, c, d, s);
        }
    }
    if (tid < 17) scnt[tid] = 0;
    if (tid < 64) bcnt[tid] = 0;
    __syncthreads();

    int j = 0, p = 0;

    // ---- phase 0: cap 2048, E16, steps 0..127 ----
    prim_run<16>(tbl, sdeath, wred, R1, tid << 4, tid, wid, j, p, 0, 128);
    compact_block<16>(tbl, smk, &scnt[16], R1, tid << 4, tid, j, 1920);
    j = 1919;

    // ---- phases E15..E3: 128 steps each, compact every 128 ----
    Chain<15>::go(tbl, smk, sdeath, wred, scnt, tid, wid, j, p, 128);
    // leaves j = 255, cap 256

    // ---- single-warp cascade: 256(E8) -> 128(E4) -> 64(E2) -> 32(E1) ----
    if (wid == 0) {
        Regs<8> Q1; reload<8>(tbl, smk, Q1, lane << 3, 256);
        prim_warp<8>(tbl, sdeath, Q1, lane << 3, lane, j, 1792, 128);
        compact_warp<8>(tbl, smk, &scnt[2], Q1, lane << 3, lane, j, 128);
        Regs<4> Q2; reload<4>(tbl, smk, Q2, lane << 2, 128); j = 127;
        prim_warp<4>(tbl, sdeath, Q2, lane << 2, lane, j, 1920, 64);
        compact_warp<4>(tbl, smk, &scnt[1], Q2, lane << 2, lane, j, 64);
        Regs<2> Q3; reload<2>(tbl, smk, Q3, lane << 1, 64); j = 63;
        prim_warp<2>(tbl, sdeath, Q3, lane << 1, lane, j, 1984, 32);
        compact_warp<2>(tbl, smk, &scnt[0], Q3, lane << 1, lane, j, 32);
        Regs<1> Q4; reload<1>(tbl, smk, Q4, lane, 32); j = 31;
        prim_warp<1>(tbl, sdeath, Q4, lane, lane, j, 2016, 31);
    }
    __syncthreads();

    // ---- d^2 -> death = sqrt(d2); pad slot 2047 with +INF ----
    #pragma unroll
    for (int e = 0; e < 16; e++) {
        int i = (tid << 4) + e;
        float d2 = sdeath[i];
        sdeath[i] = (i < NPTS - 1) ? sqrtf(d2) : inf;
    }
    __syncthreads();

    const long dgm_base = (long)b * 3 * MAXPTS * 2;                     // diagrams [B,3,100,2]
    const long bet_base = (long)B * 3 * MAXPTS * 2 + (long)b * 3 * F;   // betti    [B,3,F]

    // ---- zero-fill H1/H2 diagram slices and betti rows 1,2 ----
    for (int i = tid; i < 2 * MAXPTS * 2; i += NT)
        out[dgm_base + MAXPTS * 2 + i] = 0.0f;
    for (int i = tid; i < 2 * F; i += NT)
        out[bet_base + F + i] = 0.0f;

    // ---- Betti-0: two threads per filtration value ----
    {
        int f = tid >> 1, half = tid & 1;
        if (f < F && f < 64) {
            float ff = filt[f];
            int cnt = 0;
            int i0 = half * (NPTS / 2);
            for (int i = i0; i < i0 + NPTS / 2; i += 4) {
                float4 v = *reinterpret_cast<const float4*>(&sdeath[i]);
                cnt += (v.x <= ff) + (v.y <= ff) + (v.z <= ff) + (v.w <= ff);
            }
            atomicAdd(&bcnt[f], cnt);
        }
        // fallback for F > 64 (not expected; F = 50)
        for (int f2 = 64 + tid; f2 < F; f2 += NT) {
            float ff = filt[f2];
            int cnt = 0;
            for (int i = 0; i < NPTS; i += 4) {
                float4 v = *reinterpret_cast<const float4*>(&sdeath[i]);
                cnt += (v.x <= ff) + (v.y <= ff) + (v.z <= ff) + (v.w <= ff);
            }
            out[bet_base + f2] = (float)(NPTS - cnt);
        }
    }
    __syncthreads();
    if (tid < F && tid < 64) out[bet_base + tid] = (float)(NPTS - bcnt[tid]);
    __syncthreads();

    // ---- top-100 deaths desc: iterative max extraction ----
    int jp = -1;
    p = 0;
    const int gbase = tid << 4;
    #pragma unroll 1
    for (int k = 0; k < MAXPTS; k++) {
        float bv[16]; int bi[16];
        #pragma unroll
        for (int e = 0; e < 16; e++) {
            int gi = gbase + e;
            float v = sdeath[gi];
            bv[e] = (gi == jp || gi == NPTS - 1) ? 0.0f : v;  // mask pending + INF pad
            bi[e] = e;
        }
        #pragma unroll
        for (int st = 8; st >= 1; st >>= 1) {
            #pragma unroll
            for (int e = 0; e < st; e++) {
                bool c = bv[e+st] > bv[e];
                bv[e] = c ? bv[e+st] : bv[e];
                bi[e] = c ? bi[e+st] : bi[e];
            }
        }
        u32 ti = (u32)(gbase + bi[0]);
        u32 vb = __float_as_uint(bv[0]);
        u32 r1 = __reduce_max_sync(0xffffffffu, vb);
        if (vb == r1) wred[p][wid] = ((u64)r1 << 32) | (u64)ti;
        if (tid == 0 && jp >= 0) sdeath[jp] = 0.0f;   // persist removal

        __syncthreads();

        ulonglong2 wa = *reinterpret_cast<const ulonglong2*>(&wred[p][0]);
        ulonglong2 wb2 = *reinterpret_cast<const ulonglong2*>(&wred[p][2]);
        u64 a0 = umax64(wa.x, wa.y);
        u64 a1 = umax64(wb2.x, wb2.y);
        a0 = umax64(a0, a1);

        if (tid == 0) {
            out[dgm_base + 2 * k + 0] = 0.0f;
            out[dgm_base + 2 * k + 1] = __uint_as_float((u32)(a0 >> 32));
        }
        jp = (int)(u32)a0;
        p ^= 1;
    }
}

extern "C" void kernel_launch(void* const* d_in, const int* in_sizes, int n_in,
                              void* d_out, int out_size)
{
    const float* x    = (const float*)d_in[0];
    const float* filt = (const float*)d_in[1];
    float* out        = (float*)d_out;

    int B = in_sizes[0] / (NPTS * 3);
    int F = in_sizes[1];

    ph_kernel<<<B, NT>>>(x, filt, out, B, F);
}